// round 9
// baseline (speedup 1.0000x reference)
#include <cuda_runtime.h>
#include <cuda_fp16.h>
#include <cstdint>

// Problem dims
#define NL 16
#define DH 128
#define G4 512      // 4*H
#define BB 32
#define TT 512
#define NH 2048     // N*H
#define STRD 136    // padded halves per row (conflict-free LDS)

// x_proj scratch, GATE-INTERLEAVED: [n][t][b][j][gate] fp16, bias pre-added
__device__ __half g_xp16[(size_t)NL * TT * BB * G4];

// ---------------- mma.sync m16n8k16 (fp16 in, fp32 acc) ----------------
__device__ __forceinline__ void mma16816(float* d, const uint32_t* a,
                                         uint32_t b0, uint32_t b1) {
    asm volatile("mma.sync.aligned.m16n8k16.row.col.f32.f16.f16.f32 "
                 "{%0,%1,%2,%3}, {%4,%5,%6,%7}, {%8,%9}, {%0,%1,%2,%3};"
                 : "+f"(d[0]), "+f"(d[1]), "+f"(d[2]), "+f"(d[3])
                 : "r"(a[0]), "r"(a[1]), "r"(a[2]), "r"(a[3]), "r"(b0), "r"(b1));
}

// HW tanh (1 MUFU); sigma(x) = 0.5*tanh(x/2)+0.5
__device__ __forceinline__ float tanh_apx(float x) {
    float t;
    asm("tanh.approx.f32 %0, %1;" : "=f"(t) : "f"(x));
    return t;
}
__device__ __forceinline__ float sigm_apx(float x) {
    return fmaf(0.5f, tanh_apx(0.5f * x), 0.5f);
}

// =================================================================
// Phase 1: x_proj16[n][t][b][j][g] = W_ih[n].x + b_ih + b_hh
// grid (8 hb, 16 n) = 128 CTAs (1 wave), 512 threads.
// SMEM-staged coalesced stores, double-buffered stage (1 bar/slice).
// =================================================================
#define P1_TB 128
#define STGW 264   // stage row stride in words (256 + 8 pad)
#define P1_S_WS  0
#define P1_S_X0  (G4 * STRD * 2)                       // 139264
#define P1_S_X1  (P1_S_X0 + P1_TB * STRD * 2)          // +34816
#define P1_S_STG (P1_S_X1 + P1_TB * STRD * 2)          // +34816
#define P1_SMEM  (P1_S_STG + 2 * 8 * STGW * 4)         // +16896 = 225792

__global__ void __launch_bounds__(512, 1) wlstm_xproj(
    const float* __restrict__ x, const float* __restrict__ Wih,
    const float* __restrict__ bih, const float* __restrict__ bhh)
{
    extern __shared__ char p1smem[];
    __half*    ws  = (__half*)(p1smem + P1_S_WS);      // [512][STRD]
    __half*    xb0 = (__half*)(p1smem + P1_S_X0);      // [128][STRD]
    __half*    xb1 = (__half*)(p1smem + P1_S_X1);
    uint32_t*  stw = (uint32_t*)(p1smem + P1_S_STG);   // [2][8][STGW] words

    const int tid = threadIdx.x, wid = tid >> 5, lane = tid & 31;
    const int g0 = lane >> 2, cq = lane & 3;
    const int n = blockIdx.y, hb = blockIdx.x;

    // ---- W_ih[n] fp32 -> fp16 SMEM
    const float4* W4 = (const float4*)(Wih + (size_t)n * G4 * DH);
#pragma unroll 4
    for (int i = tid; i < G4 * DH / 4; i += 512) {
        float4 w = W4[i];
        int r = i >> 5, k = (i & 31) * 4;
        __half2 h01 = __floats2half2_rn(w.x, w.y);
        __half2 h23 = __floats2half2_rn(w.z, w.w);
        uint2 v = { *(uint32_t*)&h01, *(uint32_t*)&h23 };
        *(uint2*)(ws + r * STRD + k) = v;
    }

    // x tile loader: unit u -> (bl = u>>2, tt = u&3)
    auto load_tile = [&](int u, __half* dst) {
        int b = hb * 4 + (u >> 2), t0 = (u & 3) * P1_TB;
#pragma unroll 4
        for (int i = tid; i < P1_TB * DH / 4; i += 512) {
            int tl = i >> 5, c4 = (i & 31) * 4;
            float4 w = *(const float4*)(x + ((size_t)b * TT + t0 + tl) * NH + n * DH + c4);
            __half2 h01 = __floats2half2_rn(w.x, w.y);
            __half2 h23 = __floats2half2_rn(w.z, w.w);
            uint2 v = { *(uint32_t*)&h01, *(uint32_t*)&h23 };
            *(uint2*)(dst + tl * STRD + c4) = v;
        }
    };
    load_tile(0, xb0);
    __syncthreads();

    // ---- A-fragments: warp wid owns m-tiles {2*wid, 2*wid+1}
    uint32_t a[2][8][4];
    const uint32_t* ws32 = (const uint32_t*)ws;
#pragma unroll
    for (int ti = 0; ti < 2; ti++) {
        int r0 = (2 * wid + ti) * 16 + g0;
#pragma unroll
        for (int kc = 0; kc < 8; kc++) {
            int kw = kc * 8 + cq;
            a[ti][kc][0] = ws32[r0 * (STRD / 2) + kw];
            a[ti][kc][1] = ws32[(r0 + 8) * (STRD / 2) + kw];
            a[ti][kc][2] = ws32[r0 * (STRD / 2) + kw + 4];
            a[ti][kc][3] = ws32[(r0 + 8) * (STRD / 2) + kw + 4];
        }
    }
    float bsv[2][2];
#pragma unroll
    for (int ti = 0; ti < 2; ti++) {
        int r0 = (2 * wid + ti) * 16 + g0;
        bsv[ti][0] = bih[n * G4 + r0]     + bhh[n * G4 + r0];
        bsv[ti][1] = bih[n * G4 + r0 + 8] + bhh[n * G4 + r0 + 8];
    }

    for (int u = 0; u < 16; u++) {
        const __half* xs = (u & 1) ? xb1 : xb0;
        if (u < 15) load_tile(u + 1, (u & 1) ? xb0 : xb1);

        int b = hb * 4 + (u >> 2), t0 = (u & 3) * P1_TB;
        __half* ob = g_xp16 + ((size_t)(n * TT + t0) * BB + b) * G4;
        const uint32_t* xs32 = (const uint32_t*)xs;

        for (int nt = 0; nt < 16; nt++) {
            uint32_t* stg = stw + (nt & 1) * (8 * STGW);
            __half*   sth = (__half*)stg;
            float d[2][4];
#pragma unroll
            for (int ti = 0; ti < 2; ti++)
#pragma unroll
                for (int q = 0; q < 4; q++) d[ti][q] = 0.0f;

            int col = nt * 8 + g0;
#pragma unroll
            for (int kc = 0; kc < 8; kc++) {
                uint32_t b0 = xs32[col * (STRD / 2) + kc * 8 + cq];
                uint32_t b1 = xs32[col * (STRD / 2) + kc * 8 + cq + 4];
#pragma unroll
                for (int ti = 0; ti < 2; ti++) mma16816(d[ti], a[ti][kc], b0, b1);
            }
            // stage slice [8 t][j*4+gate] with bias folded
            int tb0 = 2 * cq;
#pragma unroll
            for (int ti = 0; ti < 2; ti++) {
                int r0 = (2 * wid + ti) * 16 + g0;
                int j = r0 & 127, gate = r0 >> 7;
                sth[(size_t)tb0 * (2 * STGW) + j * 4 + gate]             = __float2half(d[ti][0] + bsv[ti][0]);
                sth[(size_t)(tb0 + 1) * (2 * STGW) + j * 4 + gate]       = __float2half(d[ti][1] + bsv[ti][0]);
                sth[(size_t)tb0 * (2 * STGW) + (j + 8) * 4 + gate]       = __float2half(d[ti][2] + bsv[ti][1]);
                sth[(size_t)(tb0 + 1) * (2 * STGW) + (j + 8) * 4 + gate] = __float2half(d[ti][3] + bsv[ti][1]);
            }
            __syncthreads();
            // cooperative coalesced store (1 bar per slice; double-buffered)
            {
                int tl = tid >> 6, w4 = tid & 63;
                uint4 v = *(const uint4*)(stg + tl * STGW + w4 * 4);
                *(uint4*)(ob + (size_t)(nt * 8 + tl) * (BB * G4) + w4 * 8) = v;
            }
        }
        __syncthreads();   // xs reads done + prefetched tile visible
    }
}

// =================================================================
// Phase 2: persistent recurrence, WARP-LOCAL epilogue.
// grid 64 = n(16) x bc(4 of 8 batches), 256 threads (8 warps).
// Warp q owns gate tiles {q, q+8, q+16, q+24} -> thread holds all 4
// gates of its 4 states. No z exchange; ONE barrier per step.
// =================================================================
__global__ void __launch_bounds__(256, 1) wlstm_rec(
    const float* __restrict__ Whh, float* __restrict__ out)
{
    __shared__ __half hs[2][8][STRD];   // double-buffered h tile [buf][b][j]

    const int tid = threadIdx.x, wid = tid >> 5, lane = tid & 31;
    const int g0 = lane >> 2, cq = lane & 3;
    const int n = blockIdx.x >> 2, bc = blockIdx.x & 3;

    for (int i = tid; i < 2 * 8 * STRD; i += 256) ((__half*)hs)[i] = __float2half(0.0f);

    // ---- W_hh[n] -> A-fragments: gate gi tile rows gi*128 + wid*16
    uint32_t a[4][8][4];
    const float* W = Whh + (size_t)n * G4 * DH;
#pragma unroll
    for (int gi = 0; gi < 4; gi++) {
        int r0 = gi * 128 + wid * 16 + g0;
#pragma unroll
        for (int kc = 0; kc < 8; kc++) {
            int k0 = kc * 16 + cq * 2;
            float2 w00 = *(const float2*)(W + (size_t)r0 * DH + k0);
            float2 w10 = *(const float2*)(W + (size_t)(r0 + 8) * DH + k0);
            float2 w01 = *(const float2*)(W + (size_t)r0 * DH + k0 + 8);
            float2 w11 = *(const float2*)(W + (size_t)(r0 + 8) * DH + k0 + 8);
            __half2 h00 = __floats2half2_rn(w00.x, w00.y);
            __half2 h10 = __floats2half2_rn(w10.x, w10.y);
            __half2 h01 = __floats2half2_rn(w01.x, w01.y);
            __half2 h11 = __floats2half2_rn(w11.x, w11.y);
            a[gi][kc][0] = *(uint32_t*)&h00;
            a[gi][kc][1] = *(uint32_t*)&h10;
            a[gi][kc][2] = *(uint32_t*)&h01;
            a[gi][kc][3] = *(uint32_t*)&h11;
        }
    }

    // states s = jo*2 + bo : j = wid*16 + g0 + jo*8 ; b = bc*8 + 2*cq + bo
    const int j0  = wid * 16 + g0;
    const int bl0 = 2 * cq;               // local batch (= hs row, = mma N col)
    const int bg0 = bc * 8 + bl0;         // global batch

    // per-state pointers
    const __half* xqb[4];
    float* ob[4];
    int hoff[4];   // smem half-offset within a buffer
#pragma unroll
    for (int s = 0; s < 4; s++) {
        int jo = s >> 1, bo = s & 1;
        int j = j0 + jo * 8, b = bg0 + bo;
        xqb[s] = g_xp16 + ((size_t)n * TT * BB + b) * G4 + j * 4;
        ob[s]  = out + (size_t)b * TT * NH + n * DH + j;
        hoff[s] = (bl0 + bo) * STRD + j;
    }

    uint2 xpa[4], xpb[4];
#pragma unroll
    for (int s = 0; s < 4; s++) xpa[s] = *(const uint2*)xqb[s];

    float cst[4], hst[4];
#pragma unroll
    for (int s = 0; s < 4; s++) { cst[s] = 0.0f; hst[s] = 0.0f; }

    __syncthreads();

    size_t toff = 0;   // t * NH for out stores

    auto step = [&](int t, uint2 (&xpc)[4], uint2 (&xpn)[4]) {
        // prefetch x_proj(t+1) (4 gates per state in one 8B load)
        if (t + 1 < TT) {
            size_t xo = (size_t)(t + 1) * (BB * G4);
#pragma unroll
            for (int s = 0; s < 4; s++) xpn[s] = *(const uint2*)(xqb[s] + xo);
        }
        // ---- z = W_hh . h_{t-1} : 4 gate tiles, 4 independent chains
        const uint32_t* hb = (const uint32_t*)hs[t & 1];
        float d[4][4];
#pragma unroll
        for (int gi = 0; gi < 4; gi++)
#pragma unroll
            for (int q = 0; q < 4; q++) d[gi][q] = 0.0f;
#pragma unroll
        for (int kc = 0; kc < 8; kc++) {
            uint32_t b0 = hb[g0 * (STRD / 2) + kc * 8 + cq];
            uint32_t b1 = hb[g0 * (STRD / 2) + kc * 8 + cq + 4];
#pragma unroll
            for (int gi = 0; gi < 4; gi++) mma16816(d[gi], a[gi][kc], b0, b1);
        }

        // ---- warp-local epilogue: 4 states, all gates in-register
        __half* hw = (__half*)hs[(t + 1) & 1];
#pragma unroll
        for (int s = 0; s < 4; s++) {
            int q = s;   // d[gi][jo*2+bo]
            float2 f01 = __half22float2(*(__half2*)&xpc[s].x);
            float2 f23 = __half22float2(*(__half2*)&xpc[s].y);
            float zi = d[0][q] + f01.x;
            float zf = d[1][q] + f01.y;
            float zg = d[2][q] + f23.x;
            float zo = d[3][q] + f23.y;
            float ig = sigm_apx(zi);
            float fg = sigm_apx(zf);
            float gg = tanh_apx(zg);
            float og = sigm_apx(zo);
            float cv = fg * cst[s] + ig * gg;
            cst[s] = cv;
            float hv = og * tanh_apx(cv);
            hst[s] = hv;
            ob[s][toff] = hv;
            hw[hoff[s]] = __float2half(hv);
        }
        toff += NH;
        __syncthreads();   // h(t) visible; hs[t&1] reads done before t+2
    };

    for (int t = 0; t < TT; t += 2) {
        step(t, xpa, xpb);
        step(t + 1, xpb, xpa);
    }

    // h_n, c_n: out = [output | h_n | c_n]
    float* hn = out + (size_t)BB * TT * NH;
    float* cn = hn + (size_t)BB * NH;
#pragma unroll
    for (int s = 0; s < 4; s++) {
        int jo = s >> 1, bo = s & 1;
        int j = j0 + jo * 8, b = bg0 + bo;
        hn[(size_t)b * NH + n * DH + j] = hst[s];
        cn[(size_t)b * NH + n * DH + j] = cst[s];
    }
}

extern "C" void kernel_launch(void* const* d_in, const int* in_sizes, int n_in,
                              void* d_out, int out_size) {
    const float* x   = (const float*)d_in[0];
    const float* Wih = (const float*)d_in[1];
    const float* Whh = (const float*)d_in[2];
    const float* bih = (const float*)d_in[3];
    const float* bhh = (const float*)d_in[4];
    float* out = (float*)d_out;

    cudaFuncSetAttribute(wlstm_xproj,
                         cudaFuncAttributeMaxDynamicSharedMemorySize, P1_SMEM);

    dim3 g1(8, NL);   // 128 CTAs, 1 wave
    wlstm_xproj<<<g1, 512, P1_SMEM>>>(x, Wih, bih, bhh);
    wlstm_rec<<<NL * 4, 256>>>(Whh, out);
}

// round 10
// speedup vs baseline: 1.1846x; 1.1846x over previous
#include <cuda_runtime.h>
#include <cuda_fp16.h>
#include <cstdint>

// Problem dims
#define NL 16
#define DH 128
#define G4 512      // 4*H
#define BB 32
#define TT 512
#define NH 2048     // N*H
#define STRD 136    // padded halves per row (conflict-free LDS)

// x_proj scratch, GATE-INTERLEAVED: [n][t][b][j][gate] fp16, bias pre-added
__device__ __half g_xp16[(size_t)NL * TT * BB * G4];

// ---------------- mma.sync m16n8k16 (fp16 in, fp32 acc) ----------------
__device__ __forceinline__ void mma16816(float* d, const uint32_t* a,
                                         uint32_t b0, uint32_t b1) {
    asm volatile("mma.sync.aligned.m16n8k16.row.col.f32.f16.f16.f32 "
                 "{%0,%1,%2,%3}, {%4,%5,%6,%7}, {%8,%9}, {%0,%1,%2,%3};"
                 : "+f"(d[0]), "+f"(d[1]), "+f"(d[2]), "+f"(d[3])
                 : "r"(a[0]), "r"(a[1]), "r"(a[2]), "r"(a[3]), "r"(b0), "r"(b1));
}

// HW tanh (1 MUFU); sigma(x) = 0.5*tanh(x/2)+0.5
__device__ __forceinline__ float tanh_apx(float x) {
    float t;
    asm("tanh.approx.f32 %0, %1;" : "=f"(t) : "f"(x));
    return t;
}
__device__ __forceinline__ float sigm_apx(float x) {
    return fmaf(0.5f, tanh_apx(0.5f * x), 0.5f);
}

// =================================================================
// Phase 1: x_proj16[n][t][b][j][g] = W_ih[n].x + b_ih + b_hh
// grid (8 hb, 16 n) = 128 CTAs (1 wave), 512 threads.
// SMEM-staged coalesced stores, double-buffered stage (1 bar/slice).
// =================================================================
#define P1_TB 128
#define STGW 264   // stage row stride in words (256 + 8 pad)
#define P1_S_WS  0
#define P1_S_X0  (G4 * STRD * 2)                       // 139264
#define P1_S_X1  (P1_S_X0 + P1_TB * STRD * 2)          // +34816
#define P1_S_STG (P1_S_X1 + P1_TB * STRD * 2)          // +34816
#define P1_SMEM  (P1_S_STG + 2 * 8 * STGW * 4)         // +16896 = 225792

__global__ void __launch_bounds__(512, 1) wlstm_xproj(
    const float* __restrict__ x, const float* __restrict__ Wih,
    const float* __restrict__ bih, const float* __restrict__ bhh)
{
    extern __shared__ char p1smem[];
    __half*    ws  = (__half*)(p1smem + P1_S_WS);      // [512][STRD]
    __half*    xb0 = (__half*)(p1smem + P1_S_X0);      // [128][STRD]
    __half*    xb1 = (__half*)(p1smem + P1_S_X1);
    uint32_t*  stw = (uint32_t*)(p1smem + P1_S_STG);   // [2][8][STGW] words

    const int tid = threadIdx.x, wid = tid >> 5, lane = tid & 31;
    const int g0 = lane >> 2, cq = lane & 3;
    const int n = blockIdx.y, hb = blockIdx.x;

    // ---- W_ih[n] fp32 -> fp16 SMEM
    const float4* W4 = (const float4*)(Wih + (size_t)n * G4 * DH);
#pragma unroll 4
    for (int i = tid; i < G4 * DH / 4; i += 512) {
        float4 w = W4[i];
        int r = i >> 5, k = (i & 31) * 4;
        __half2 h01 = __floats2half2_rn(w.x, w.y);
        __half2 h23 = __floats2half2_rn(w.z, w.w);
        uint2 v = { *(uint32_t*)&h01, *(uint32_t*)&h23 };
        *(uint2*)(ws + r * STRD + k) = v;
    }

    // x tile loader: unit u -> (bl = u>>2, tt = u&3)
    auto load_tile = [&](int u, __half* dst) {
        int b = hb * 4 + (u >> 2), t0 = (u & 3) * P1_TB;
#pragma unroll 4
        for (int i = tid; i < P1_TB * DH / 4; i += 512) {
            int tl = i >> 5, c4 = (i & 31) * 4;
            float4 w = *(const float4*)(x + ((size_t)b * TT + t0 + tl) * NH + n * DH + c4);
            __half2 h01 = __floats2half2_rn(w.x, w.y);
            __half2 h23 = __floats2half2_rn(w.z, w.w);
            uint2 v = { *(uint32_t*)&h01, *(uint32_t*)&h23 };
            *(uint2*)(dst + tl * STRD + c4) = v;
        }
    };
    load_tile(0, xb0);
    __syncthreads();

    // ---- A-fragments: warp wid owns m-tiles {2*wid, 2*wid+1}
    uint32_t a[2][8][4];
    const uint32_t* ws32 = (const uint32_t*)ws;
#pragma unroll
    for (int ti = 0; ti < 2; ti++) {
        int r0 = (2 * wid + ti) * 16 + g0;
#pragma unroll
        for (int kc = 0; kc < 8; kc++) {
            int kw = kc * 8 + cq;
            a[ti][kc][0] = ws32[r0 * (STRD / 2) + kw];
            a[ti][kc][1] = ws32[(r0 + 8) * (STRD / 2) + kw];
            a[ti][kc][2] = ws32[r0 * (STRD / 2) + kw + 4];
            a[ti][kc][3] = ws32[(r0 + 8) * (STRD / 2) + kw + 4];
        }
    }
    float bsv[2][2];
#pragma unroll
    for (int ti = 0; ti < 2; ti++) {
        int r0 = (2 * wid + ti) * 16 + g0;
        bsv[ti][0] = bih[n * G4 + r0]     + bhh[n * G4 + r0];
        bsv[ti][1] = bih[n * G4 + r0 + 8] + bhh[n * G4 + r0 + 8];
    }

    for (int u = 0; u < 16; u++) {
        const __half* xs = (u & 1) ? xb1 : xb0;
        if (u < 15) load_tile(u + 1, (u & 1) ? xb0 : xb1);

        int b = hb * 4 + (u >> 2), t0 = (u & 3) * P1_TB;
        __half* ob = g_xp16 + ((size_t)(n * TT + t0) * BB + b) * G4;
        const uint32_t* xs32 = (const uint32_t*)xs;

        for (int nt = 0; nt < 16; nt++) {
            uint32_t* stg = stw + (nt & 1) * (8 * STGW);
            __half*   sth = (__half*)stg;
            float d[2][4];
#pragma unroll
            for (int ti = 0; ti < 2; ti++)
#pragma unroll
                for (int q = 0; q < 4; q++) d[ti][q] = 0.0f;

            int col = nt * 8 + g0;
#pragma unroll
            for (int kc = 0; kc < 8; kc++) {
                uint32_t b0 = xs32[col * (STRD / 2) + kc * 8 + cq];
                uint32_t b1 = xs32[col * (STRD / 2) + kc * 8 + cq + 4];
#pragma unroll
                for (int ti = 0; ti < 2; ti++) mma16816(d[ti], a[ti][kc], b0, b1);
            }
            // stage slice [8 t][j*4+gate] with bias folded
            int tb0 = 2 * cq;
#pragma unroll
            for (int ti = 0; ti < 2; ti++) {
                int r0 = (2 * wid + ti) * 16 + g0;
                int j = r0 & 127, gate = r0 >> 7;
                sth[(size_t)tb0 * (2 * STGW) + j * 4 + gate]             = __float2half(d[ti][0] + bsv[ti][0]);
                sth[(size_t)(tb0 + 1) * (2 * STGW) + j * 4 + gate]       = __float2half(d[ti][1] + bsv[ti][0]);
                sth[(size_t)tb0 * (2 * STGW) + (j + 8) * 4 + gate]       = __float2half(d[ti][2] + bsv[ti][1]);
                sth[(size_t)(tb0 + 1) * (2 * STGW) + (j + 8) * 4 + gate] = __float2half(d[ti][3] + bsv[ti][1]);
            }
            __syncthreads();
            // cooperative coalesced store (1 bar per slice; double-buffered)
            {
                int tl = tid >> 6, w4 = tid & 63;
                uint4 v = *(const uint4*)(stg + tl * STGW + w4 * 4);
                *(uint4*)(ob + (size_t)(nt * 8 + tl) * (BB * G4) + w4 * 8) = v;
            }
        }
        __syncthreads();   // xs reads done + prefetched tile visible
    }
}

// =================================================================
// Phase 2: persistent recurrence, WARP-LOCAL epilogue, FULL CHIP.
// grid 128 = n(16) x bc(8 of 4 batches), 256 threads (8 warps).
// Batches sit in EVEN mma N-columns -> every thread owns exactly
// one real batch (2 states). Warp q owns gate tiles {q,q+8,q+16,q+24}
// -> all 4 gates in-thread. No z exchange; ONE barrier per step.
// =================================================================
__global__ void __launch_bounds__(256, 1) wlstm_rec(
    const float* __restrict__ Whh, float* __restrict__ out)
{
    __shared__ __half hs[2][8][STRD];   // [buf][N-col slot][j]; odd slots = 0 pad

    const int tid = threadIdx.x, wid = tid >> 5, lane = tid & 31;
    const int g0 = lane >> 2, cq = lane & 3;
    const int n = blockIdx.x >> 3, bc = blockIdx.x & 7;

    for (int i = tid; i < 2 * 8 * STRD; i += 256) ((__half*)hs)[i] = __float2half(0.0f);

    // ---- W_hh[n] -> A-fragments: gate gi tile rows gi*128 + wid*16
    uint32_t a[4][8][4];
    const float* W = Whh + (size_t)n * G4 * DH;
#pragma unroll
    for (int gi = 0; gi < 4; gi++) {
        int r0 = gi * 128 + wid * 16 + g0;
#pragma unroll
        for (int kc = 0; kc < 8; kc++) {
            int k0 = kc * 16 + cq * 2;
            float2 w00 = *(const float2*)(W + (size_t)r0 * DH + k0);
            float2 w10 = *(const float2*)(W + (size_t)(r0 + 8) * DH + k0);
            float2 w01 = *(const float2*)(W + (size_t)r0 * DH + k0 + 8);
            float2 w11 = *(const float2*)(W + (size_t)(r0 + 8) * DH + k0 + 8);
            __half2 h00 = __floats2half2_rn(w00.x, w00.y);
            __half2 h10 = __floats2half2_rn(w10.x, w10.y);
            __half2 h01 = __floats2half2_rn(w01.x, w01.y);
            __half2 h11 = __floats2half2_rn(w11.x, w11.y);
            a[gi][kc][0] = *(uint32_t*)&h00;
            a[gi][kc][1] = *(uint32_t*)&h10;
            a[gi][kc][2] = *(uint32_t*)&h01;
            a[gi][kc][3] = *(uint32_t*)&h11;
        }
    }

    // thread's batch: local bl = cq (N-col 2*cq), global b = bc*4 + cq
    // states s = jo in {0,1}: j = wid*16 + g0 + jo*8
    const int j0 = wid * 16 + g0;
    const int b  = bc * 4 + cq;

    const __half* xqb[2];
    float* ob[2];
    int hoff[2];
#pragma unroll
    for (int s = 0; s < 2; s++) {
        int j = j0 + s * 8;
        xqb[s] = g_xp16 + ((size_t)n * TT * BB + b) * G4 + j * 4;
        ob[s]  = out + (size_t)b * TT * NH + n * DH + j;
        hoff[s] = (2 * cq) * STRD + j;      // even N-col slot
    }

    uint2 xpa[2], xpb[2];
#pragma unroll
    for (int s = 0; s < 2; s++) xpa[s] = *(const uint2*)xqb[s];

    float cst[2] = {0.0f, 0.0f}, hst[2] = {0.0f, 0.0f};

    __syncthreads();

    size_t toff = 0;

    auto step = [&](int t, uint2 (&xpc)[2], uint2 (&xpn)[2]) {
        // prefetch x_proj(t+1): 4 gates per state in one 8B load
        if (t + 1 < TT) {
            size_t xo = (size_t)(t + 1) * (BB * G4);
#pragma unroll
            for (int s = 0; s < 2; s++) xpn[s] = *(const uint2*)(xqb[s] + xo);
        }
        // ---- z = W_hh . h_{t-1} : 4 gate tiles, independent chains
        const uint32_t* hb = (const uint32_t*)hs[t & 1];
        float d[4][4];
#pragma unroll
        for (int gi = 0; gi < 4; gi++)
#pragma unroll
            for (int q = 0; q < 4; q++) d[gi][q] = 0.0f;
#pragma unroll
        for (int kc = 0; kc < 8; kc++) {
            uint32_t b0 = hb[g0 * (STRD / 2) + kc * 8 + cq];
            uint32_t b1 = hb[g0 * (STRD / 2) + kc * 8 + cq + 4];
#pragma unroll
            for (int gi = 0; gi < 4; gi++) mma16816(d[gi], a[gi][kc], b0, b1);
        }

        // ---- warp-local epilogue: 2 states, all gates in-register
        // D frag: q=0 -> (row g0, col 2cq) ; q=2 -> (row g0+8, col 2cq)
        __half* hw = (__half*)hs[(t + 1) & 1];
#pragma unroll
        for (int s = 0; s < 2; s++) {
            int q = s * 2;
            float2 f01 = __half22float2(*(__half2*)&xpc[s].x);
            float2 f23 = __half22float2(*(__half2*)&xpc[s].y);
            float zi = d[0][q] + f01.x;
            float zf = d[1][q] + f01.y;
            float zg = d[2][q] + f23.x;
            float zo = d[3][q] + f23.y;
            float ig = sigm_apx(zi);
            float fg = sigm_apx(zf);
            float gg = tanh_apx(zg);
            float og = sigm_apx(zo);
            float cv = fg * cst[s] + ig * gg;
            cst[s] = cv;
            float hv = og * tanh_apx(cv);
            hst[s] = hv;
            ob[s][toff] = hv;
            hw[hoff[s]] = __float2half(hv);
        }
        toff += NH;
        __syncthreads();   // h(t) visible; hs[t&1] reads done before t+2
    };

    for (int t = 0; t < TT; t += 2) {
        step(t, xpa, xpb);
        step(t + 1, xpb, xpa);
    }

    // h_n, c_n: out = [output | h_n | c_n]
    float* hn = out + (size_t)BB * TT * NH;
    float* cn = hn + (size_t)BB * NH;
#pragma unroll
    for (int s = 0; s < 2; s++) {
        int j = j0 + s * 8;
        hn[(size_t)b * NH + n * DH + j] = hst[s];
        cn[(size_t)b * NH + n * DH + j] = cst[s];
    }
}

extern "C" void kernel_launch(void* const* d_in, const int* in_sizes, int n_in,
                              void* d_out, int out_size) {
    const float* x   = (const float*)d_in[0];
    const float* Wih = (const float*)d_in[1];
    const float* Whh = (const float*)d_in[2];
    const float* bih = (const float*)d_in[3];
    const float* bhh = (const float*)d_in[4];
    float* out = (float*)d_out;

    cudaFuncSetAttribute(wlstm_xproj,
                         cudaFuncAttributeMaxDynamicSharedMemorySize, P1_SMEM);

    dim3 g1(8, NL);   // 128 CTAs, 1 wave
    wlstm_xproj<<<g1, 512, P1_SMEM>>>(x, Wih, bih, bhh);
    wlstm_rec<<<NL * 8, 256>>>(Whh, out);
}